// round 16
// baseline (speedup 1.0000x reference)
#include <cuda_runtime.h>
#include <math.h>

#define S_LEN  1024
#define B_SIZE 512
#define NTAG   48
#define PF     4

__device__ float g_llh[B_SIZE];

__global__ void __launch_bounds__(64)
crf_forward_kernel(const float* __restrict__ emissions,
                   const int* __restrict__ tags,
                   const int* __restrict__ mask,
                   const float* __restrict__ start_t,
                   const float* __restrict__ end_t,
                   const float* __restrict__ trans)
{
    const int b    = blockIdx.x;
    const int j    = threadIdx.x;          // 0..63, tags are 0..47
    const int lane = j & 31;
    const int wid  = j >> 5;
    const bool act = (j < NTAG);

    __shared__ __align__(16) float v_sh[2][64];
    __shared__ float wred[2];
    __shared__ float red[4];

    // E column in registers: Ecol[i] = exp(T[i][j])
    float Ecol[NTAG];
#pragma unroll
    for (int i = 0; i < NTAG; i++)
        Ecol[i] = act ? __expf(trans[i * NTAG + j]) : 0.f;
    const float expEnd = act ? __expf(end_t[j]) : 0.f;

    // ---- t = 0 ----
    float em = act ? emissions[(size_t)b * NTAG + j] : -1e30f;
    const int tag0 = tags[b];
    float nm = 0.f;
    float score0 = (act ? start_t[j] : -1e30f) + em;
    if (j == tag0) nm = score0;
    v_sh[0][j] = act ? __expf(score0) : 0.f;
    v_sh[1][j] = 0.f;

    float M = 0.f;
    int prev_tag = tag0;
    int last_tag = tag0;
    int cur = 0;
    int nupd = 0;

    // ---- prefetch: emissions ring depth PF; tags/mask one step ahead ----
    float pf[PF];
#pragma unroll
    for (int k = 0; k < PF; k++) {
        int t = 1 + k;
        pf[t & (PF - 1)] = act ? emissions[((size_t)t * B_SIZE + b) * NTAG + j] : -1e30f;
    }
    int tg_n = tags[1 * B_SIZE + b];
    int m_n  = mask[1 * B_SIZE + b];
    __syncthreads();

    for (int t = 1; t < S_LEN; t++) {
        const int tg  = tg_n;
        const int m_t = m_n;
        // issue next-step scalar loads immediately (consumed next iteration)
        const int tn1 = (t + 1 < S_LEN) ? t + 1 : S_LEN - 1;
        tg_n = tags[tn1 * B_SIZE + b];
        m_n  = mask[tn1 * B_SIZE + b];

        const int slot = t & (PF - 1);
        const float e_em = __expf(pf[slot]);
        const float em_t = pf[slot];
        const int tnp = (t + PF < S_LEN) ? t + PF : S_LEN - 1;
        pf[slot] = act ? emissions[((size_t)tnp * B_SIZE + b) * NTAG + j] : -1e30f;

        // S[j] = sum_i v[i] * E[i][j]
        const float* vv = v_sh[cur];
        float s0 = 0.f, s1 = 0.f, s2 = 0.f, s3 = 0.f;
#pragma unroll
        for (int i = 0; i < NTAG; i += 4) {
            const float4 v4 = *(const float4*)(vv + i);
            s0 = fmaf(v4.x, Ecol[i + 0], s0);
            s1 = fmaf(v4.y, Ecol[i + 1], s1);
            s2 = fmaf(v4.z, Ecol[i + 2], s2);
            s3 = fmaf(v4.w, Ecol[i + 3], s3);
        }
        float w = ((s0 + s1) + (s2 + s3)) * e_em;

        if (m_t) {
            // fused numerator: lane matching the gold tag accumulates
            if (j == tg) nm += em_t + trans[prev_tag * NTAG + j];
            last_tag = tg;
            nupd++;
            if ((nupd & 7) == 0) {
                // renormalize: r = max_j w ; M += log r ; w /= r
                float r = w;
#pragma unroll
                for (int o = 16; o > 0; o >>= 1)
                    r = fmaxf(r, __shfl_xor_sync(0xffffffffu, r, o));
                if (lane == 0) wred[wid] = r;
                __syncthreads();
                r = fmaxf(fmaxf(wred[0], wred[1]), 1e-30f);
                M += __logf(r);
                w *= (1.f / r);
            }
            v_sh[cur ^ 1][j] = w;
        }
        prev_tag = tg;
        __syncthreads();
        if (m_t) cur ^= 1;
    }

    // ---- finalize ----
    float contrib = v_sh[cur][j] * expEnd;   // 0 for j>=48
    float nsum = nm;
#pragma unroll
    for (int o = 16; o > 0; o >>= 1) {
        contrib += __shfl_xor_sync(0xffffffffu, contrib, o);
        nsum    += __shfl_xor_sync(0xffffffffu, nsum, o);
    }
    if (lane == 0) { red[wid] = contrib; red[wid + 2] = nsum; }
    __syncthreads();
    if (j == 0) {
        const float denom = M + __logf(red[0] + red[1]);
        const float numer = red[2] + red[3] + end_t[last_tag];
        g_llh[b] = numer - denom;
    }
}

__global__ void __launch_bounds__(512)
crf_reduce_kernel(float* __restrict__ out)
{
    __shared__ float sh[512];
    const int t = threadIdx.x;
    sh[t] = g_llh[t];
    __syncthreads();
#pragma unroll
    for (int o = 256; o > 0; o >>= 1) {
        if (t < o) sh[t] += sh[t + o];
        __syncthreads();
    }
    if (t == 0) out[0] = sh[0] * (1.f / (float)B_SIZE);
}

extern "C" void kernel_launch(void* const* d_in, const int* in_sizes, int n_in,
                              void* d_out, int out_size)
{
    const float* emissions = (const float*)d_in[0];
    const int*   tags      = (const int*)d_in[1];
    const int*   mask      = (const int*)d_in[2];
    const float* start_t   = (const float*)d_in[3];
    const float* end_t     = (const float*)d_in[4];
    const float* trans     = (const float*)d_in[5];

    crf_forward_kernel<<<B_SIZE, 64>>>(emissions, tags, mask, start_t, end_t, trans);
    crf_reduce_kernel<<<1, 512>>>((float*)d_out);
}

// round 17
// speedup vs baseline: 4.1301x; 4.1301x over previous
#include <cuda_runtime.h>
#include <math.h>

#define S_LEN  1024
#define B_SIZE 512
#define NTAG   48
#define PF     4
#define TMID   511
#define NCHUNK 64
#define CHUNK  (S_LEN / NCHUNK)

__device__ float g_fa[B_SIZE][64];    // forward alpha (unnorm) at TMID
__device__ float g_bu[B_SIZE][64];    // backward beta-u (unnorm) at TMID
__device__ float g_Mf[B_SIZE];
__device__ float g_Mb[B_SIZE];
__device__ float g_pnum[NCHUNK][B_SIZE];
__device__ int   g_pcnt[NCHUNK][B_SIZE];

__device__ __forceinline__ unsigned long long pack2f(float lo, float hi) {
    unsigned long long r;
    asm("mov.b64 %0, {%1, %2};" : "=l"(r) : "f"(lo), "f"(hi));
    return r;
}
__device__ __forceinline__ void unpack2f(unsigned long long v, float& lo, float& hi) {
    asm("mov.b64 {%0, %1}, %2;" : "=f"(lo), "=f"(hi) : "l"(v));
}
__device__ __forceinline__ void ffma2(unsigned long long& acc,
                                      unsigned long long a, unsigned long long b) {
    asm("fma.rn.f32x2 %0, %1, %2, %0;" : "+l"(acc) : "l"(a), "l"(b));
}

// ---- one warp = one half-chain; blocks 0..511 forward, 512..1023 backward ----
// (verbatim the R8 component measured at ~175us / 91 cyc per chain-step per SM)
__global__ void __launch_bounds__(32)
crf_fwdbwd_kernel(const float* __restrict__ emissions,
                  const int* __restrict__ mask,
                  const float* __restrict__ start_t,
                  const float* __restrict__ end_t,
                  const float* __restrict__ trans)
{
    const int dir = blockIdx.x >> 9;      // 0 = fwd, 1 = bwd
    const int b   = blockIdx.x & (B_SIZE - 1);
    const int l   = threadIdx.x;
    const int j0  = l;
    const int j1  = l + 32;
    const bool a1 = (j1 < NTAG);

    __shared__ __align__(16) float2 sh2[64];

    unsigned long long E2[NTAG];
    float M = 0.f;
    int nupd = 0;
    float w0, w1;

    if (dir == 0) {
        // E columns: E2[i] = { exp(T[i][j0]), exp(T[i][j1]) }
#pragma unroll
        for (int i = 0; i < NTAG; i++) {
            float e0 = __expf(trans[i * NTAG + j0]);
            float e1 = a1 ? __expf(trans[i * NTAG + j1]) : 0.f;
            E2[i] = pack2f(e0, e1);
        }
        // t = 0
        float em0 = emissions[(size_t)b * NTAG + j0];
        float em1 = a1 ? emissions[(size_t)b * NTAG + j1] : 0.f;
        float s1i = a1 ? start_t[j1] : -1e30f;
        w0 = __expf(start_t[j0] + em0);
        w1 = a1 ? __expf(s1i + em1) : 0.f;
        sh2[j0] = make_float2(w0, w0);
        sh2[j1] = make_float2(w1, w1);

        float pf0[PF], pf1[PF];
#pragma unroll
        for (int k = 0; k < PF; k++) {
            int t = 1 + k;
            pf0[t & (PF - 1)] = emissions[((size_t)t * B_SIZE + b) * NTAG + j0];
            pf1[t & (PF - 1)] = a1 ? emissions[((size_t)t * B_SIZE + b) * NTAG + j1] : 0.f;
        }
        unsigned mbits;
        {
            int mt = mask[(size_t)l * B_SIZE + b];
            mbits = __ballot_sync(0xffffffffu, mt != 0);
        }
        __syncwarp();

#pragma unroll 4
        for (int t = 1; t <= TMID; t++) {
            if ((t & 31) == 0) {
                int mt = mask[(size_t)(t + l) * B_SIZE + b];
                mbits = __ballot_sync(0xffffffffu, mt != 0);
            }
            const int m_t = (mbits >> (t & 31)) & 1;

            const int slot = t & (PF - 1);
            const float e0 = __expf(pf0[slot]);
            const float e1 = __expf(pf1[slot]);
            int tn = t + PF; if (tn > TMID) tn = TMID;
            pf0[slot] = emissions[((size_t)tn * B_SIZE + b) * NTAG + j0];
            pf1[slot] = a1 ? emissions[((size_t)tn * B_SIZE + b) * NTAG + j1] : 0.f;

            unsigned long long acc[6] = {0ull,0ull,0ull,0ull,0ull,0ull};
            const ulonglong2* vp = (const ulonglong2*)sh2;
#pragma unroll
            for (int i = 0; i < NTAG; i += 2) {
                ulonglong2 v2 = vp[i >> 1];
                ffma2(acc[(i >> 1) % 6], v2.x, E2[i]);
                ffma2(acc[((i >> 1) + 3) % 6], v2.y, E2[i + 1]);
            }
            float s0 = 0.f, s1 = 0.f;
#pragma unroll
            for (int k = 0; k < 6; k++) { float lo, hi; unpack2f(acc[k], lo, hi); s0 += lo; s1 += hi; }
            float nw0 = s0 * e0, nw1 = s1 * e1;

            if (m_t) {
                w0 = nw0; w1 = nw1;
                if (((++nupd) & 7) == 0) {
                    float r = fmaxf(w0, w1);
#pragma unroll
                    for (int o = 16; o > 0; o >>= 1)
                        r = fmaxf(r, __shfl_xor_sync(0xffffffffu, r, o));
                    r = fmaxf(r, 1e-30f);
                    M += __logf(r);
                    float inv = 1.f / r;
                    w0 *= inv; w1 *= inv;
                }
                sh2[j0] = make_float2(w0, w0);
                sh2[j1] = make_float2(w1, w1);
            }
            __syncwarp();
        }
        g_fa[b][j0] = w0;
        g_fa[b][j1] = w1;
        if (l == 0) g_Mf[b] = M;
    } else {
        // E rows: E2[k] = { exp(T[i0][k]), exp(T[i1][k]) }, i0=l, i1=l+32
#pragma unroll
        for (int k = 0; k < NTAG; k++) {
            float e0 = __expf(trans[j0 * NTAG + k]);
            float e1 = a1 ? __expf(trans[j1 * NTAG + k]) : 0.f;
            E2[k] = pack2f(e0, e1);
        }
        // init: u_1023 = exp(end); stored z = e_em(1023) * u_1023
        {
            float em0 = emissions[((size_t)(S_LEN - 1) * B_SIZE + b) * NTAG + j0];
            float em1 = a1 ? emissions[((size_t)(S_LEN - 1) * B_SIZE + b) * NTAG + j1] : 0.f;
            w0 = __expf(end_t[j0]);
            w1 = a1 ? __expf(end_t[a1 ? j1 : 0]) : 0.f;
            float z0 = w0 * __expf(em0);
            float z1 = a1 ? (w1 * __expf(em1)) : 0.f;
            sh2[j0] = make_float2(z0, z0);
            sh2[j1] = make_float2(z1, z1);
        }
        float pf0[PF], pf1[PF];
#pragma unroll
        for (int k = 0; k < PF; k++) {
            int t = 1022 - k;
            pf0[t & (PF - 1)] = emissions[((size_t)t * B_SIZE + b) * NTAG + j0];
            pf1[t & (PF - 1)] = a1 ? emissions[((size_t)t * B_SIZE + b) * NTAG + j1] : 0.f;
        }
        unsigned mbits;
        {
            int mt = mask[(size_t)(992 + l) * B_SIZE + b];   // covers m[992..1023]
            mbits = __ballot_sync(0xffffffffu, mt != 0);
        }
        __syncwarp();

#pragma unroll 4
        for (int t = 1022; t >= TMID; t--) {
            const int tp1 = t + 1;
            if ((tp1 & 31) == 31) {
                int base = tp1 - 31;
                int mt = mask[(size_t)(base + l) * B_SIZE + b];
                mbits = __ballot_sync(0xffffffffu, mt != 0);
            }
            const int m_t = (mbits >> (tp1 & 31)) & 1;   // mask[t+1]

            const int slot = t & (PF - 1);
            const float e0 = __expf(pf0[slot]);
            const float e1 = __expf(pf1[slot]);
            int tn = t - PF; if (tn < TMID) tn = TMID;
            pf0[slot] = emissions[((size_t)tn * B_SIZE + b) * NTAG + j0];
            pf1[slot] = a1 ? emissions[((size_t)tn * B_SIZE + b) * NTAG + j1] : 0.f;

            if (m_t) {
                unsigned long long acc[6] = {0ull,0ull,0ull,0ull,0ull,0ull};
                const ulonglong2* vp = (const ulonglong2*)sh2;
#pragma unroll
                for (int k = 0; k < NTAG; k += 2) {
                    ulonglong2 v2 = vp[k >> 1];
                    ffma2(acc[(k >> 1) % 6], v2.x, E2[k]);
                    ffma2(acc[((k >> 1) + 3) % 6], v2.y, E2[k + 1]);
                }
                float s0 = 0.f, s1 = 0.f;
#pragma unroll
                for (int kk = 0; kk < 6; kk++) { float lo, hi; unpack2f(acc[kk], lo, hi); s0 += lo; s1 += hi; }
                w0 = s0; w1 = s1;
                if (((++nupd) & 7) == 0) {
                    float r = fmaxf(w0, w1);
#pragma unroll
                    for (int o = 16; o > 0; o >>= 1)
                        r = fmaxf(r, __shfl_xor_sync(0xffffffffu, r, o));
                    r = fmaxf(r, 1e-30f);
                    M += __logf(r);
                    float inv = 1.f / r;
                    w0 *= inv; w1 *= inv;
                }
            }
            // store z = e_em(t) * u  (recomputed from registers — mask-safe)
            if (t > TMID) {
                float z0 = w0 * e0;
                float z1 = w1 * e1;
                sh2[j0] = make_float2(z0, z0);
                sh2[j1] = make_float2(z1, z1);
            }
            __syncwarp();
        }
        g_bu[b][j0] = w0;
        g_bu[b][j1] = w1;
        if (l == 0) g_Mb[b] = M;
    }
}

// ---- numerator partials: coalesced over batch, 64 blocks (proven fast) ----
__global__ void __launch_bounds__(B_SIZE)
crf_num_kernel(const float* __restrict__ emissions,
               const int* __restrict__ tags,
               const int* __restrict__ mask,
               const float* __restrict__ start_t,
               const float* __restrict__ trans)
{
    const int b  = threadIdx.x;
    const int c  = blockIdx.x;
    const int t0 = c * CHUNK;

    float acc = 0.f;
    int cnt = 0;
    int tp = (t0 > 0) ? tags[(t0 - 1) * B_SIZE + b] : 0;
#pragma unroll
    for (int k = 0; k < CHUNK; k++) {
        int t  = t0 + k;
        int tg = tags[t * B_SIZE + b];
        int m  = mask[t * B_SIZE + b];
        cnt += m;
        if (t == 0) {
            acc += start_t[tg] + emissions[(size_t)b * NTAG + tg];
        } else {
            acc += (trans[tp * NTAG + tg] +
                    emissions[((size_t)t * B_SIZE + b) * NTAG + tg]) * (float)m;
        }
        tp = tg;
    }
    g_pnum[c][b] = acc;
    g_pcnt[c][b] = cnt;
}

// ---- final: end-term + alpha.beta dot + mean ----
__global__ void __launch_bounds__(B_SIZE)
crf_reduce_kernel(float* __restrict__ out,
                  const int* __restrict__ tags,
                  const float* __restrict__ end_t)
{
    __shared__ float sh[B_SIZE];
    const int b = threadIdx.x;

    float num = 0.f;
    int cnt = 0;
#pragma unroll
    for (int c = 0; c < NCHUNK; c++) { num += g_pnum[c][b]; cnt += g_pcnt[c][b]; }
    num += end_t[tags[(cnt - 1) * B_SIZE + b]];

    float dot = 0.f;
    const float4* fa = (const float4*)g_fa[b];
    const float4* bu = (const float4*)g_bu[b];
#pragma unroll
    for (int k = 0; k < 12; k++) {
        float4 x = fa[k], y = bu[k];
        dot += x.x * y.x + x.y * y.y + x.z * y.z + x.w * y.w;
    }
    const float den = g_Mf[b] + g_Mb[b] + __logf(dot);

    sh[b] = num - den;
    __syncthreads();
#pragma unroll
    for (int o = B_SIZE / 2; o > 0; o >>= 1) {
        if (b < o) sh[b] += sh[b + o];
        __syncthreads();
    }
    if (b == 0) out[0] = sh[0] * (1.f / (float)B_SIZE);
}

extern "C" void kernel_launch(void* const* d_in, const int* in_sizes, int n_in,
                              void* d_out, int out_size)
{
    const float* emissions = (const float*)d_in[0];
    const int*   tags      = (const int*)d_in[1];
    const int*   mask      = (const int*)d_in[2];
    const float* start_t   = (const float*)d_in[3];
    const float* end_t     = (const float*)d_in[4];
    const float* trans     = (const float*)d_in[5];

    crf_fwdbwd_kernel<<<2 * B_SIZE, 32>>>(emissions, mask, start_t, end_t, trans);
    crf_num_kernel<<<NCHUNK, B_SIZE>>>(emissions, tags, mask, start_t, trans);
    crf_reduce_kernel<<<1, B_SIZE>>>((float*)d_out, tags, end_t);
}